// round 1
// baseline (speedup 1.0000x reference)
#include <cuda_runtime.h>
#include <cstdint>
#include <cstddef>

// Problem constants
#define D     1024
#define BATCH 32

// Tiling
#define BM 128
#define BN 128
#define BK 32
#define AST 36    // A smem row stride (floats), padded for conflict-free frag loads
#define BST 132   // B smem row stride (floats)
#define STAGE_A (BM * AST)              // 4608 floats
#define STAGE_B (BK * BST)              // 4224 floats
#define SMEM_FLOATS (2 * STAGE_A + 2 * STAGE_B)
#define SMEM_BYTES  (SMEM_FLOATS * 4)   // 70656 bytes -> dynamic smem

// Scratch for q = Wp@Q + bp  (allocation-free: device global)
__device__ float g_q[(size_t)BATCH * D * D];

// ---------------- helpers ----------------

__device__ __forceinline__ void cp16(float* dst, const float* src) {
    unsigned d = (unsigned)__cvta_generic_to_shared(dst);
    asm volatile("cp.async.cg.shared.global [%0], [%1], 16;\n" :: "r"(d), "l"(src));
}
__device__ __forceinline__ void cp_commit() { asm volatile("cp.async.commit_group;\n" ::); }
__device__ __forceinline__ void cp_wait_all() { asm volatile("cp.async.wait_group 0;\n" ::); }

__device__ __forceinline__ unsigned f2tf32(float x) {
    unsigned r;
    asm("cvt.rna.tf32.f32 %0, %1;" : "=r"(r) : "f"(x));
    return r;
}

__device__ __forceinline__ void mma_tf32(float c[4], const unsigned a[4], const unsigned b[2]) {
    asm volatile(
        "mma.sync.aligned.m16n8k8.row.col.f32.tf32.tf32.f32 "
        "{%0,%1,%2,%3}, {%4,%5,%6,%7}, {%8,%9}, {%0,%1,%2,%3};\n"
        : "+f"(c[0]), "+f"(c[1]), "+f"(c[2]), "+f"(c[3])
        : "r"(a[0]), "r"(a[1]), "r"(a[2]), "r"(a[3]),
          "r"(b[0]), "r"(b[1]));
}

// Load a BM x BK tile of A (row-major, ld = D) into smem with stride AST.
__device__ __forceinline__ void load_A_tile(float* sA, const float* __restrict__ A,
                                            int row0, int kk, int tid) {
    int r = tid >> 3;       // 0..31
    int s = tid & 7;        // 0..7  (8 x 16B segments per 32-float row)
    const float* src = A + (size_t)(row0 + r) * D + kk + s * 4;
    float* dst = sA + r * AST + s * 4;
#pragma unroll
    for (int i = 0; i < 4; i++)
        cp16(dst + i * 32 * AST, src + (size_t)i * 32 * D);
}

// Load a BK x BN tile of B (row-major, ld = D) into smem with stride BST.
__device__ __forceinline__ void load_B_tile(float* sB, const float* __restrict__ Bp,
                                            int kk, int col0, int tid) {
    int r = tid >> 5;       // 0..7
    int s = tid & 31;       // 0..31 (32 x 16B segments per 128-float row)
    const float* src = Bp + (size_t)(kk + r) * D + col0 + s * 4;
    float* dst = sB + r * BST + s * 4;
#pragma unroll
    for (int i = 0; i < 4; i++)
        cp16(dst + i * 8 * BST, src + (size_t)i * 8 * D);
}

// Compute one BM x BN x BK slab. Warp tile 64x32 via m16n8k8 tf32 mma.
__device__ __forceinline__ void compute_tile(const float* sA, const float* sB,
                                             float acc[4][4][4],
                                             int wm, int wn, int g, int tg) {
#pragma unroll
    for (int ks = 0; ks < 4; ks++) {
        const int k0 = ks * 8;
        unsigned afr[4][4];
#pragma unroll
        for (int mt = 0; mt < 4; mt++) {
            const int r = wm + mt * 16 + g;
            afr[mt][0] = f2tf32(sA[r * AST + k0 + tg]);
            afr[mt][1] = f2tf32(sA[(r + 8) * AST + k0 + tg]);
            afr[mt][2] = f2tf32(sA[r * AST + k0 + tg + 4]);
            afr[mt][3] = f2tf32(sA[(r + 8) * AST + k0 + tg + 4]);
        }
#pragma unroll
        for (int nt = 0; nt < 4; nt++) {
            const int c = wn + nt * 8 + g;
            unsigned bfr[2];
            bfr[0] = f2tf32(sB[(k0 + tg) * BST + c]);
            bfr[1] = f2tf32(sB[(k0 + tg + 4) * BST + c]);
#pragma unroll
            for (int mt = 0; mt < 4; mt++)
                mma_tf32(acc[mt][nt], afr[mt], bfr);
        }
    }
}

// MODE 0: g_q = A0 @ B0[b] + bias[col]                        (q = Wp@Q + bp)
// MODE 1: out = relu(A0@B0[b] + A1@g_q[b] + bias[col]) * g_q  (fused dual-K GEMM)
template <int MODE>
__global__ void __launch_bounds__(256, 2)
fused_gemm(const float* __restrict__ A0, const float* __restrict__ B0,
           const float* __restrict__ A1, const float* __restrict__ bias,
           float* __restrict__ outp) {
    extern __shared__ float smem[];
    float* sAbuf[2] = { smem, smem + STAGE_A };
    float* sBbuf[2] = { smem + 2 * STAGE_A, smem + 2 * STAGE_A + STAGE_B };

    const int b  = blockIdx.z;
    const int bm = blockIdx.y * BM;
    const int bn = blockIdx.x * BN;
    const int tid  = threadIdx.x;
    const int lane = tid & 31;
    const int warp = tid >> 5;
    const int wm = (warp >> 2) * 64;   // 2 warp rows
    const int wn = (warp & 3) * 32;    // 4 warp cols
    const int g  = lane >> 2;
    const int tg = lane & 3;

    const size_t bofs = (size_t)b * D * D;
    const float* Bb0 = B0 + bofs;
    const float* Bb1 = g_q + bofs;     // second-source B operand (MODE 1)

    float acc[4][4][4];
#pragma unroll
    for (int mt = 0; mt < 4; mt++)
#pragma unroll
        for (int nt = 0; nt < 4; nt++)
#pragma unroll
            for (int i = 0; i < 4; i++)
                acc[mt][nt][i] = 0.0f;

    const int KT = (MODE == 0) ? (D / BK) : (2 * D / BK);

    // Prologue: stage 0
    load_A_tile(sAbuf[0], A0, bm, 0, tid);
    load_B_tile(sBbuf[0], Bb0, 0, bn, tid);
    cp_commit();

    for (int kt = 0; kt < KT; kt++) {
        cp_wait_all();
        __syncthreads();

        const int nk = kt + 1;
        if (nk < KT) {
            float* dA = sAbuf[nk & 1];
            float* dB = sBbuf[nk & 1];
            if (MODE == 1 && nk >= D / BK) {
                const int kk = (nk - D / BK) * BK;
                load_A_tile(dA, A1, bm, kk, tid);
                load_B_tile(dB, Bb1, kk, bn, tid);
            } else {
                const int kk = nk * BK;
                load_A_tile(dA, A0, bm, kk, tid);
                load_B_tile(dB, Bb0, kk, bn, tid);
            }
        }
        cp_commit();

        compute_tile(sAbuf[kt & 1], sBbuf[kt & 1], acc, wm, wn, g, tg);
    }

    // Epilogue
#pragma unroll
    for (int mt = 0; mt < 4; mt++) {
#pragma unroll
        for (int nt = 0; nt < 4; nt++) {
            const int row = bm + wm + mt * 16 + g;
            const int col = bn + wn + nt * 8 + 2 * tg;
            const size_t i0 = bofs + (size_t)row * D + col;
            const size_t i1 = i0 + (size_t)8 * D;
            const float bv0 = bias[col];
            const float bv1 = bias[col + 1];
            if (MODE == 0) {
                float2 v0 = make_float2(acc[mt][nt][0] + bv0, acc[mt][nt][1] + bv1);
                float2 v1 = make_float2(acc[mt][nt][2] + bv0, acc[mt][nt][3] + bv1);
                *reinterpret_cast<float2*>(g_q + i0) = v0;
                *reinterpret_cast<float2*>(g_q + i1) = v1;
            } else {
                const float2 q0 = *reinterpret_cast<const float2*>(g_q + i0);
                const float2 q1 = *reinterpret_cast<const float2*>(g_q + i1);
                float z0 = fmaxf(acc[mt][nt][0] + bv0, 0.0f);
                float z1 = fmaxf(acc[mt][nt][1] + bv1, 0.0f);
                float z2 = fmaxf(acc[mt][nt][2] + bv0, 0.0f);
                float z3 = fmaxf(acc[mt][nt][3] + bv1, 0.0f);
                *reinterpret_cast<float2*>(outp + i0) = make_float2(z0 * q0.x, z1 * q0.y);
                *reinterpret_cast<float2*>(outp + i1) = make_float2(z2 * q1.x, z3 * q1.y);
            }
        }
    }
}

extern "C" void kernel_launch(void* const* d_in, const int* in_sizes, int n_in,
                              void* d_out, int out_size) {
    (void)in_sizes; (void)n_in; (void)out_size;
    // metadata order: K, Q, M, ht, Wp, bp, W3, W4, b3, Wd, bd
    // K / ht / Wd / bd are dead code in the reference (scores/softmax deleted).
    const float* Q  = (const float*)d_in[1];
    const float* M  = (const float*)d_in[2];
    const float* Wp = (const float*)d_in[4];
    const float* bp = (const float*)d_in[5];
    const float* W3 = (const float*)d_in[6];
    const float* W4 = (const float*)d_in[7];
    const float* b3 = (const float*)d_in[8];
    float* out = (float*)d_out;

    cudaFuncSetAttribute(fused_gemm<0>, cudaFuncAttributeMaxDynamicSharedMemorySize, SMEM_BYTES);
    cudaFuncSetAttribute(fused_gemm<1>, cudaFuncAttributeMaxDynamicSharedMemorySize, SMEM_BYTES);

    dim3 grid(D / BN, D / BM, BATCH);   // (8, 8, 32)
    dim3 block(256);

    // Pass 1: q = Wp @ Q + bp  -> g_q
    fused_gemm<0><<<grid, block, SMEM_BYTES>>>(Wp, Q, nullptr, bp, nullptr);
    // Pass 2: out = relu(W3@M + W4@q + b3) * q  (single fused K=2048 GEMM)
    fused_gemm<1><<<grid, block, SMEM_BYTES>>>(W3, M, W4, b3, out);
}

// round 2
// speedup vs baseline: 1.2959x; 1.2959x over previous
#include <cuda_runtime.h>
#include <cstdint>
#include <cstddef>

// Problem constants
#define D     1024
#define BATCH 32
#define NELEM ((size_t)BATCH * D * D)   // 33,554,432

// Tiling
#define BM 128
#define BN 128
#define BK 32
#define AST 36    // A smem row stride (floats)
#define BST 136   // B smem row stride (tg*8+g -> conflict-free fragment loads)
#define STAGE_A (BM * AST)              // 4608
#define STAGE_B (BK * BST)              // 4352
#define SMEM_FLOATS (2 * STAGE_A + 2 * STAGE_B)
#define SMEM_BYTES  (SMEM_FLOATS * 4)   // 71680 bytes

// Allocation-free scratch (device globals)
__device__ __align__(16) float    g_q [NELEM];        // exact q (epilogue gate)
__device__ __align__(16) unsigned g_qt[NELEM];        // tf32(q)  (pass-2 B operand)
__device__ __align__(16) unsigned g_Qt[NELEM];        // tf32(Q)
__device__ __align__(16) unsigned g_Mt[NELEM];        // tf32(M)
__device__ __align__(16) unsigned g_Wt[3u * 1024 * 1024];  // tf32(Wp|W3|W4)

// ---------------- helpers ----------------

__device__ __forceinline__ void cp16(void* dst, const void* src) {
    unsigned d = (unsigned)__cvta_generic_to_shared(dst);
    asm volatile("cp.async.cg.shared.global [%0], [%1], 16;\n" :: "r"(d), "l"(src));
}
__device__ __forceinline__ void cp_commit() { asm volatile("cp.async.commit_group;\n" ::); }
__device__ __forceinline__ void cp_wait_all() { asm volatile("cp.async.wait_group 0;\n" ::); }

__device__ __forceinline__ unsigned f2tf32(float x) {
    unsigned r;
    asm("cvt.rna.tf32.f32 %0, %1;" : "=r"(r) : "f"(x));
    return r;
}

__device__ __forceinline__ void mma_tf32(float c[4], const unsigned a[4], const unsigned b[2]) {
    asm volatile(
        "mma.sync.aligned.m16n8k8.row.col.f32.tf32.tf32.f32 "
        "{%0,%1,%2,%3}, {%4,%5,%6,%7}, {%8,%9}, {%0,%1,%2,%3};\n"
        : "+f"(c[0]), "+f"(c[1]), "+f"(c[2]), "+f"(c[3])
        : "r"(a[0]), "r"(a[1]), "r"(a[2]), "r"(a[3]),
          "r"(b[0]), "r"(b[1]));
}

// ---------------- pre-convert: fp32 -> tf32 bit pattern ----------------

__global__ void cvt_tf32_kernel(const float4* __restrict__ src,
                                uint4* __restrict__ dst) {
    size_t i = (size_t)blockIdx.x * blockDim.x + threadIdx.x;
    float4 v = src[i];
    uint4 o;
    o.x = f2tf32(v.x); o.y = f2tf32(v.y); o.z = f2tf32(v.z); o.w = f2tf32(v.w);
    dst[i] = o;
}

// ---------------- loaders (128 threads) ----------------

// A: BM x BK tile (row-major src, ld=D) -> smem stride AST
__device__ __forceinline__ void load_A_tile(unsigned* sA, const unsigned* __restrict__ A,
                                            int row0, int kk, int tid) {
    const int s  = tid & 7;        // 8 x 16B per 32-word row
    const int r0 = tid >> 3;       // 0..15
    const unsigned* src = A + (size_t)(row0 + r0) * D + kk + s * 4;
    unsigned* dst = sA + r0 * AST + s * 4;
#pragma unroll
    for (int i = 0; i < 8; i++)
        cp16(dst + i * 16 * AST, src + (size_t)i * 16 * D);
}

// B: BK x BN tile (row-major src, ld=D) -> smem stride BST
__device__ __forceinline__ void load_B_tile(unsigned* sB, const unsigned* __restrict__ Bp,
                                            int kk, int col0, int tid) {
    const int s  = tid & 31;       // 32 x 16B per 128-word row
    const int r0 = tid >> 5;       // 0..3
    const unsigned* src = Bp + (size_t)(kk + r0) * D + col0 + s * 4;
    unsigned* dst = sB + r0 * BST + s * 4;
#pragma unroll
    for (int i = 0; i < 8; i++)
        cp16(dst + i * 4 * BST, src + (size_t)i * 4 * D);
}

// ---------------- main GEMM ----------------
// 128x128 block tile, 4 warps, 64x64 warp tile, tf32 m16n8k8.
// MODE 0: g_q = A0 @ B0[b] + bias ; g_qt = tf32(g_q)
// MODE 1: out = relu(A0@B0[b] + A1@g_qt[b] + bias) * g_q
template <int MODE>
__global__ void __launch_bounds__(128, 2)
fused_gemm(const unsigned* __restrict__ A0, const unsigned* __restrict__ B0,
           const unsigned* __restrict__ A1, const float* __restrict__ bias,
           float* __restrict__ outp) {
    extern __shared__ unsigned smem[];
    unsigned* sAbuf[2] = { smem, smem + STAGE_A };
    unsigned* sBbuf[2] = { smem + 2 * STAGE_A, smem + 2 * STAGE_A + STAGE_B };

    const int b  = blockIdx.z;
    const int bm = blockIdx.y * BM;
    const int bn = blockIdx.x * BN;
    const int tid  = threadIdx.x;
    const int lane = tid & 31;
    const int warp = tid >> 5;     // 0..3
    const int wm = (warp >> 1) * 64;
    const int wn = (warp & 1) * 64;
    const int g  = lane >> 2;
    const int tg = lane & 3;

    const size_t bofs = (size_t)b * D * D;
    const unsigned* Bb0 = B0 + bofs;
    const unsigned* Bb1 = g_qt + bofs;

    float acc[4][8][4];
#pragma unroll
    for (int mt = 0; mt < 4; mt++)
#pragma unroll
        for (int nt = 0; nt < 8; nt++)
#pragma unroll
            for (int i = 0; i < 4; i++)
                acc[mt][nt][i] = 0.0f;

    const int KT = (MODE == 0) ? (D / BK) : (2 * D / BK);

    load_A_tile(sAbuf[0], A0, bm, 0, tid);
    load_B_tile(sBbuf[0], Bb0, 0, bn, tid);
    cp_commit();

    for (int kt = 0; kt < KT; kt++) {
        cp_wait_all();
        __syncthreads();

        const int nk = kt + 1;
        if (nk < KT) {
            unsigned* dA = sAbuf[nk & 1];
            unsigned* dB = sBbuf[nk & 1];
            if (MODE == 1 && nk >= D / BK) {
                const int kk = (nk - D / BK) * BK;
                load_A_tile(dA, A1, bm, kk, tid);
                load_B_tile(dB, Bb1, kk, bn, tid);
            } else {
                const int kk = nk * BK;
                load_A_tile(dA, A0, bm, kk, tid);
                load_B_tile(dB, Bb0, kk, bn, tid);
            }
        }
        cp_commit();

        const unsigned* sA = sAbuf[kt & 1];
        const unsigned* sB = sBbuf[kt & 1];
#pragma unroll
        for (int ks = 0; ks < 4; ks++) {
            const int k0 = ks * 8;
            unsigned afr[4][4];
#pragma unroll
            for (int mt = 0; mt < 4; mt++) {
                const int r = wm + mt * 16 + g;
                afr[mt][0] = sA[r * AST + k0 + tg];
                afr[mt][1] = sA[(r + 8) * AST + k0 + tg];
                afr[mt][2] = sA[r * AST + k0 + tg + 4];
                afr[mt][3] = sA[(r + 8) * AST + k0 + tg + 4];
            }
#pragma unroll
            for (int nt = 0; nt < 8; nt++) {
                const int c = wn + nt * 8 + g;
                unsigned bfr[2];
                bfr[0] = sB[(k0 + tg) * BST + c];
                bfr[1] = sB[(k0 + tg + 4) * BST + c];
#pragma unroll
                for (int mt = 0; mt < 4; mt++)
                    mma_tf32(acc[mt][nt], afr[mt], bfr);
            }
        }
    }

    // Epilogue
#pragma unroll
    for (int mt = 0; mt < 4; mt++) {
#pragma unroll
        for (int nt = 0; nt < 8; nt++) {
            const int row = bm + wm + mt * 16 + g;
            const int col = bn + wn + nt * 8 + 2 * tg;
            const size_t i0 = bofs + (size_t)row * D + col;
            const size_t i1 = i0 + (size_t)8 * D;
            const float bv0 = bias[col];
            const float bv1 = bias[col + 1];
            if (MODE == 0) {
                float z0 = acc[mt][nt][0] + bv0;
                float z1 = acc[mt][nt][1] + bv1;
                float z2 = acc[mt][nt][2] + bv0;
                float z3 = acc[mt][nt][3] + bv1;
                *reinterpret_cast<float2*>(g_q + i0) = make_float2(z0, z1);
                *reinterpret_cast<float2*>(g_q + i1) = make_float2(z2, z3);
                *reinterpret_cast<uint2*>(g_qt + i0) = make_uint2(f2tf32(z0), f2tf32(z1));
                *reinterpret_cast<uint2*>(g_qt + i1) = make_uint2(f2tf32(z2), f2tf32(z3));
            } else {
                const float2 q0 = *reinterpret_cast<const float2*>(g_q + i0);
                const float2 q1 = *reinterpret_cast<const float2*>(g_q + i1);
                float z0 = fmaxf(acc[mt][nt][0] + bv0, 0.0f);
                float z1 = fmaxf(acc[mt][nt][1] + bv1, 0.0f);
                float z2 = fmaxf(acc[mt][nt][2] + bv0, 0.0f);
                float z3 = fmaxf(acc[mt][nt][3] + bv1, 0.0f);
                *reinterpret_cast<float2*>(outp + i0) = make_float2(z0 * q0.x, z1 * q0.y);
                *reinterpret_cast<float2*>(outp + i1) = make_float2(z2 * q1.x, z3 * q1.y);
            }
        }
    }
}

extern "C" void kernel_launch(void* const* d_in, const int* in_sizes, int n_in,
                              void* d_out, int out_size) {
    (void)in_sizes; (void)n_in; (void)out_size;
    // metadata order: K, Q, M, ht, Wp, bp, W3, W4, b3, Wd, bd
    // K / ht / Wd / bd are dead code (scores/softmax deleted in reference).
    const float* Q  = (const float*)d_in[1];
    const float* M  = (const float*)d_in[2];
    const float* Wp = (const float*)d_in[4];
    const float* bp = (const float*)d_in[5];
    const float* W3 = (const float*)d_in[6];
    const float* W4 = (const float*)d_in[7];
    const float* b3 = (const float*)d_in[8];
    float* out = (float*)d_out;

    unsigned* dQt; cudaGetSymbolAddress((void**)&dQt, g_Qt);
    unsigned* dMt; cudaGetSymbolAddress((void**)&dMt, g_Mt);
    unsigned* dWt; cudaGetSymbolAddress((void**)&dWt, g_Wt);

    // Pre-convert operands to tf32 bit patterns (removes all in-loop CVTs)
    {
        const int T = 256;
        size_t n4 = NELEM / 4;                       // 8,388,608
        cvt_tf32_kernel<<<(unsigned)(n4 / T), T>>>((const float4*)Q, (uint4*)dQt);
        cvt_tf32_kernel<<<(unsigned)(n4 / T), T>>>((const float4*)M, (uint4*)dMt);
        size_t w4 = (size_t)(1024 * 1024) / 4;       // 262,144
        cvt_tf32_kernel<<<(unsigned)(w4 / T), T>>>((const float4*)Wp, (uint4*)(dWt));
        cvt_tf32_kernel<<<(unsigned)(w4 / T), T>>>((const float4*)W3, (uint4*)(dWt + (1u << 20)));
        cvt_tf32_kernel<<<(unsigned)(w4 / T), T>>>((const float4*)W4, (uint4*)(dWt + (2u << 20)));
    }

    cudaFuncSetAttribute(fused_gemm<0>, cudaFuncAttributeMaxDynamicSharedMemorySize, SMEM_BYTES);
    cudaFuncSetAttribute(fused_gemm<1>, cudaFuncAttributeMaxDynamicSharedMemorySize, SMEM_BYTES);

    dim3 grid(D / BN, D / BM, BATCH);   // (8, 8, 32)
    dim3 block(128);

    // Pass 1: q = Wp @ Q + bp  -> g_q (exact) + g_qt (tf32)
    fused_gemm<0><<<grid, block, SMEM_BYTES>>>(dWt, dQt, nullptr, bp, nullptr);
    // Pass 2: out = relu(W3@M + W4@q + b3) * q
    fused_gemm<1><<<grid, block, SMEM_BYTES>>>(dWt + (1u << 20), dMt,
                                               dWt + (2u << 20), b3, out);
}

// round 5
// speedup vs baseline: 1.5014x; 1.1586x over previous
#include <cuda_runtime.h>
#include <cstdint>
#include <cstddef>

// ---------------- problem constants ----------------
#define D      1024
#define BATCH  32
#define NELEM  ((size_t)BATCH * D * D)

// ---------------- tiling ----------------
#define BM 256
#define BN 128
#define BK 32
#define STAGES 3
#define A_STAGE ((BM / 16) * (BK / 8) * 32 * 16)   // 32768 bytes
#define B_STAGE ((BN / 8) * (BK / 16) * 32 * 16)   // 16384 bytes
#define STAGE_BYTES (A_STAGE + B_STAGE)            // 49152
#define SMEM_BYTES (STAGES * STAGE_BYTES)          // 147456

// ---------------- device scratch (allocation-free) ----------------
// A-fragment order tf32 weights: PA[mblk][kblk][lane][4]
__device__ __align__(16) unsigned g_PA[3u * 1024 * 1024];   // Wp | W3 | W4
// B-fragment order tf32 activations: PB[b][nblk][k16][lane][4]
__device__ __align__(16) unsigned g_PQ[NELEM];
__device__ __align__(16) unsigned g_PM[NELEM];
__device__ __align__(16) unsigned g_Pq[NELEM];
// exact q (pass-2 gating)
__device__ __align__(16) float    g_q [NELEM];

// ---------------- helpers ----------------
__device__ __forceinline__ unsigned f2tf32(float x) {
    unsigned r; asm("cvt.rna.tf32.f32 %0, %1;" : "=r"(r) : "f"(x)); return r;
}
__device__ __forceinline__ uint32_t smem_u32(const void* p) {
    uint32_t a;
    asm("{ .reg .u64 t; cvta.to.shared.u64 t, %1; cvt.u32.u64 %0, t; }" : "=r"(a) : "l"(p));
    return a;
}
__device__ __forceinline__ void cp16(uint32_t daddr, const void* src) {
    asm volatile("cp.async.cg.shared.global [%0], [%1], 16;\n" :: "r"(daddr), "l"(src));
}
__device__ __forceinline__ void cp_commit() { asm volatile("cp.async.commit_group;\n" ::); }
__device__ __forceinline__ void cp_wait1()  { asm volatile("cp.async.wait_group 1;\n" ::); }

__device__ __forceinline__ uint4 lds128(uint32_t addr) {
    uint4 v;
    asm volatile("ld.shared.v4.u32 {%0,%1,%2,%3}, [%4];"
                 : "=r"(v.x), "=r"(v.y), "=r"(v.z), "=r"(v.w) : "r"(addr));
    return v;
}
__device__ __forceinline__ void mma_tf32(float c[4], uint4 a, unsigned b0, unsigned b1) {
    asm volatile(
        "mma.sync.aligned.m16n8k8.row.col.f32.tf32.tf32.f32 "
        "{%0,%1,%2,%3}, {%4,%5,%6,%7}, {%8,%9}, {%0,%1,%2,%3};\n"
        : "+f"(c[0]), "+f"(c[1]), "+f"(c[2]), "+f"(c[3])
        : "r"(a.x), "r"(a.y), "r"(a.z), "r"(a.w), "r"(b0), "r"(b1));
}

// ---------------- pre-permutation kernels ----------------
// A-frag order: PA[mblk(64)][kblk(128)][lane(32)][4], tf32 bits.
// slots: A[m0+g][k0+tg], A[m0+8+g][k0+tg], A[m0+g][k0+4+tg], A[m0+8+g][k0+4+tg]
__global__ void permA_kernel(const float* __restrict__ W, unsigned* __restrict__ PA) {
    int t = blockIdx.x * blockDim.x + threadIdx.x;       // 0 .. 2^18-1
    int lane = t & 31, kblk = (t >> 5) & 127, mblk = t >> 12;
    int g = lane >> 2, tg = lane & 3;
    int m0 = mblk * 16 + g, k0 = kblk * 8 + tg;
    uint4 o;
    o.x = f2tf32(W[(size_t)m0 * D + k0]);
    o.y = f2tf32(W[(size_t)(m0 + 8) * D + k0]);
    o.z = f2tf32(W[(size_t)m0 * D + k0 + 4]);
    o.w = f2tf32(W[(size_t)(m0 + 8) * D + k0 + 4]);
    reinterpret_cast<uint4*>(PA)[t] = o;
}

// B-frag order: PB[b][nblk(128)][k16(64)][lane(32)][4], tf32 bits.
// slots: B[k0+tg][n], B[k0+4+tg][n], B[k0+8+tg][n], B[k0+12+tg][n]  (n = n0+g)
__global__ void permB_kernel(const float* __restrict__ X, unsigned* __restrict__ PB) {
    int t = blockIdx.x * blockDim.x + threadIdx.x;       // 0 .. 2^18-1 per batch
    int b = blockIdx.y;
    const float* Xb = X + (size_t)b * D * D;
    int lane = t & 31, k16 = (t >> 5) & 63, nblk = t >> 11;
    int g = lane >> 2, tg = lane & 3;
    int n = nblk * 8 + g, k0 = k16 * 16 + tg;
    uint4 o;
    o.x = f2tf32(Xb[(size_t)k0 * D + n]);
    o.y = f2tf32(Xb[(size_t)(k0 + 4) * D + n]);
    o.z = f2tf32(Xb[(size_t)(k0 + 8) * D + n]);
    o.w = f2tf32(Xb[(size_t)(k0 + 12) * D + n]);
    reinterpret_cast<uint4*>(PB + (size_t)b * D * D)[t] = o;
}

// ---------------- main GEMM ----------------
// 256x128 CTA tile, 8 warps (64x64 each), BK=32, 3-stage cp.async.
// chunks 0..SPLIT-1 use (A0,B0); SPLIT..KT-1 use (A1,B1).
// MODE 0: g_q = acc + bias (exact), g_Pq = tf32 B-frag order
// MODE 1: out = relu(acc + bias) * g_q
template <int MODE, int KT, int SPLIT>
__global__ void __launch_bounds__(256, 1)
gemm_tf32(const unsigned* __restrict__ A0, const unsigned* __restrict__ B0,
          const unsigned* __restrict__ A1, const unsigned* __restrict__ B1,
          const float* __restrict__ bias, float* __restrict__ outp) {
    extern __shared__ char smem[];
    const uint32_t sbase = smem_u32(smem);

    const int tid  = threadIdx.x;
    const int lane = tid & 31;
    const int wid  = tid >> 5;

    const int b      = blockIdx.z;
    const int bmblk  = blockIdx.y * (BM / 16);   // 16-row block base
    const int bnblk  = blockIdx.x * (BN / 8);    // 8-col block base
    const size_t boff = (size_t)b * D * D;

    const char* PBb0 = (const char*)(B0 + boff);
    const char* PBb1 = (const char*)(B1 + boff);

    // loader thread mapping
    const int mbA = tid >> 4;      // 0..15  (mblk within tile)
    const int inA = tid & 15;
    const int nbB = tid >> 4;      // 0..15  (nblk within tile)
    const int inB = tid & 15;

    float acc[4][8][4];
#pragma unroll
    for (int mt = 0; mt < 4; mt++)
#pragma unroll
        for (int nt = 0; nt < 8; nt++)
#pragma unroll
            for (int i = 0; i < 4; i++) acc[mt][nt][i] = 0.0f;

    auto load_chunk = [&](int c) {
        const int s = c % STAGES;
        const uint32_t sa = sbase + s * STAGE_BYTES;
        const uint32_t sb = sa + A_STAGE;
        const char* Abase; const char* Bbase; int cc;
        if (c < SPLIT) { Abase = (const char*)A0; Bbase = PBb0; cc = c; }
        else           { Abase = (const char*)A1; Bbase = PBb1; cc = c - SPLIT; }
        // A: PA[(bmblk+mbA)][cc*4 .. cc*4+3][*][*] = 2KB contiguous per mbA
        const char* srcA = Abase + (((size_t)(bmblk + mbA) * 128 + cc * 4) << 9) + inA * 16;
        const uint32_t dA = sa + mbA * 2048 + inA * 16;
#pragma unroll
        for (int i = 0; i < 8; i++) cp16(dA + i * 256, srcA + i * 256);
        // B: PB[(bnblk+nbB)][cc*2 .. cc*2+1][*][*] = 1KB contiguous per nbB
        const char* srcB = Bbase + (((size_t)(bnblk + nbB) * 64 + cc * 2) << 9) + inB * 16;
        const uint32_t dB = sb + nbB * 1024 + inB * 16;
#pragma unroll
        for (int i = 0; i < 4; i++) cp16(dB + i * 256, srcB + i * 256);
    };

    const int wm4 = (wid >> 1) * 4;   // mblk base within tile for this warp
    const int wn8 = (wid & 1) * 8;    // nblk base within tile for this warp
    const uint32_t laneoff = lane * 16;

    // prologue
    load_chunk(0); cp_commit();
    load_chunk(1); cp_commit();

    for (int c = 0; c < KT; c++) {
        cp_wait1();
        __syncthreads();

        const uint32_t sa = sbase + (c % STAGES) * STAGE_BYTES;
        const uint32_t sb = sa + A_STAGE;
#pragma unroll
        for (int k16 = 0; k16 < 2; k16++) {
            uint4 bfr[8];
#pragma unroll
            for (int nt = 0; nt < 8; nt++)
                bfr[nt] = lds128(sb + (wn8 + nt) * 1024 + k16 * 512 + laneoff);
#pragma unroll
            for (int half = 0; half < 2; half++) {
                const int ks = k16 * 2 + half;
                uint4 afr[4];
#pragma unroll
                for (int mt = 0; mt < 4; mt++)
                    afr[mt] = lds128(sa + (wm4 + mt) * 2048 + ks * 512 + laneoff);
#pragma unroll
                for (int nt = 0; nt < 8; nt++) {
                    const unsigned b0 = half ? bfr[nt].z : bfr[nt].x;
                    const unsigned b1 = half ? bfr[nt].w : bfr[nt].y;
#pragma unroll
                    for (int mt = 0; mt < 4; mt++)
                        mma_tf32(acc[mt][nt], afr[mt], b0, b1);
                }
            }
        }

        if (c + 2 < KT) load_chunk(c + 2);
        cp_commit();
    }

    // ---------------- epilogue ----------------
    const int g  = lane >> 2;
    const int tg = lane & 3;
    const int bm = blockIdx.y * BM;
    const int bn = blockIdx.x * BN;
    const int wm = (wid >> 1) * 64;
    const int wn = (wid & 1) * 64;

#pragma unroll
    for (int mt = 0; mt < 4; mt++) {
#pragma unroll
        for (int nt = 0; nt < 8; nt++) {
            const int row = bm + wm + mt * 16 + g;
            const int col = bn + wn + nt * 8 + 2 * tg;
            const size_t i0 = boff + (size_t)row * D + col;
            const size_t i1 = i0 + (size_t)8 * D;
            const float bv0 = __ldg(bias + col);
            const float bv1 = __ldg(bias + col + 1);
            if (MODE == 0) {
                const float z0 = acc[mt][nt][0] + bv0;
                const float z1 = acc[mt][nt][1] + bv1;
                const float z2 = acc[mt][nt][2] + bv0;
                const float z3 = acc[mt][nt][3] + bv1;
                *reinterpret_cast<float2*>(g_q + i0) = make_float2(z0, z1);
                *reinterpret_cast<float2*>(g_q + i1) = make_float2(z2, z3);
                // B-frag order tf32 writes (q is pass-2's B operand: k=row, n=col)
                {
                    const int nblk0 = col >> 3, gp0 = col & 7;
                    const int nblk1 = (col + 1) >> 3, gp1 = (col + 1) & 7;
                    const int k16a = row >> 4, ra = row & 15;
                    const int k16b = (row + 8) >> 4, rb = (row + 8) & 15;
                    const size_t ia0 = boff + (((size_t)(nblk0 * 64 + k16a) * 32 + gp0 * 4 + (ra & 3)) << 2) + (ra >> 2);
                    const size_t ia1 = boff + (((size_t)(nblk1 * 64 + k16a) * 32 + gp1 * 4 + (ra & 3)) << 2) + (ra >> 2);
                    const size_t ib0 = boff + (((size_t)(nblk0 * 64 + k16b) * 32 + gp0 * 4 + (rb & 3)) << 2) + (rb >> 2);
                    const size_t ib1 = boff + (((size_t)(nblk1 * 64 + k16b) * 32 + gp1 * 4 + (rb & 3)) << 2) + (rb >> 2);
                    g_Pq[ia0] = f2tf32(z0);
                    g_Pq[ia1] = f2tf32(z1);
                    g_Pq[ib0] = f2tf32(z2);
                    g_Pq[ib1] = f2tf32(z3);
                }
            } else {
                const float2 q0 = *reinterpret_cast<const float2*>(g_q + i0);
                const float2 q1 = *reinterpret_cast<const float2*>(g_q + i1);
                const float z0 = fmaxf(acc[mt][nt][0] + bv0, 0.0f);
                const float z1 = fmaxf(acc[mt][nt][1] + bv1, 0.0f);
                const float z2 = fmaxf(acc[mt][nt][2] + bv0, 0.0f);
                const float z3 = fmaxf(acc[mt][nt][3] + bv1, 0.0f);
                *reinterpret_cast<float2*>(outp + i0) = make_float2(z0 * q0.x, z1 * q0.y);
                *reinterpret_cast<float2*>(outp + i1) = make_float2(z2 * q1.x, z3 * q1.y);
            }
        }
    }
}

// ---------------- host launcher ----------------
extern "C" void kernel_launch(void* const* d_in, const int* in_sizes, int n_in,
                              void* d_out, int out_size) {
    (void)in_sizes; (void)n_in; (void)out_size;
    // metadata order: K, Q, M, ht, Wp, bp, W3, W4, b3, Wd, bd
    // K / ht / Wd / bd are dead code (scores/softmax deleted in reference).
    const float* Q  = (const float*)d_in[1];
    const float* M  = (const float*)d_in[2];
    const float* Wp = (const float*)d_in[4];
    const float* bp = (const float*)d_in[5];
    const float* W3 = (const float*)d_in[6];
    const float* W4 = (const float*)d_in[7];
    const float* b3 = (const float*)d_in[8];
    float* out = (float*)d_out;

    unsigned* dPA; cudaGetSymbolAddress((void**)&dPA, g_PA);
    unsigned* dPQ; cudaGetSymbolAddress((void**)&dPQ, g_PQ);
    unsigned* dPM; cudaGetSymbolAddress((void**)&dPM, g_PM);
    unsigned* dPq; cudaGetSymbolAddress((void**)&dPq, g_Pq);

    // pre-permute operands into fragment order (tf32 bits)
    permA_kernel<<<1024, 256>>>(Wp, dPA);
    permA_kernel<<<1024, 256>>>(W3, dPA + (1u << 20));
    permA_kernel<<<1024, 256>>>(W4, dPA + (2u << 20));
    {
        dim3 g(1024, BATCH);
        permB_kernel<<<g, 256>>>(Q, dPQ);
        permB_kernel<<<g, 256>>>(M, dPM);
    }

    cudaFuncSetAttribute(gemm_tf32<0, 32, 32>, cudaFuncAttributeMaxDynamicSharedMemorySize, SMEM_BYTES);
    cudaFuncSetAttribute(gemm_tf32<1, 64, 32>, cudaFuncAttributeMaxDynamicSharedMemorySize, SMEM_BYTES);

    dim3 grid(D / BN, D / BM, BATCH);   // (8, 4, 32)
    dim3 block(256);

    // Pass 1: q = Wp @ Q + bp  -> g_q exact + g_Pq frag-order tf32
    gemm_tf32<0, 32, 32><<<grid, block, SMEM_BYTES>>>(dPA, dPQ, dPA, dPQ, bp, nullptr);
    // Pass 2: out = relu(W3@M + W4@q + b3) * q  (fused K=2048)
    gemm_tf32<1, 64, 32><<<grid, block, SMEM_BYTES>>>(dPA + (1u << 20), dPM,
                                                      dPA + (2u << 20), dPq, b3, out);
}